// round 1
// baseline (speedup 1.0000x reference)
#include <cuda_runtime.h>
#include <math.h>

#define EPSV 1e-4f
#define B_ROWS 8192
#define F_DIM 512
#define P_DIM 64
#define C_DIM 100
#define ROWS 32
#define KC 64
#define SSI_STRIDE 65

// Precomputed, batch-independent tables (scratch via __device__ globals; no allocs).
__device__ float g_wT[F_DIM * P_DIM];   // w transposed, k-major [512][64]
__device__ float g_u[P_DIM * C_DIM];    // normalized beta^2 rows
__device__ float g_wnorm[P_DIM];
__device__ float g_gamma[P_DIM];
__device__ float g_alpha[P_DIM];

__global__ void precompute_kernel(const float* __restrict__ w,
                                  const float* __restrict__ xi,
                                  const float* __restrict__ eta,
                                  const float* __restrict__ beta) {
    int t = threadIdx.x;
    // transpose w into k-major layout for conflict-free SMEM staging later
    for (int idx = t; idx < P_DIM * F_DIM; idx += blockDim.x) {
        int p = idx / F_DIM, k = idx - p * F_DIM;
        g_wT[k * P_DIM + p] = w[idx];
    }
    if (t < P_DIM) {
        // ||w_p||^2 with two-level summation (keeps absolute error << 1e-2)
        float tot = 0.f;
        for (int c0 = 0; c0 < F_DIM; c0 += 64) {
            float s = 0.f;
            #pragma unroll 8
            for (int k = 0; k < 64; k++) {
                float v = w[t * F_DIM + c0 + k];
                s = fmaf(v, v, s);
            }
            tot += s;
        }
        g_wnorm[t] = tot;
        float e = eta[t];
        g_gamma[t] = e * e;
        g_alpha[t] = 1.f / (1.f + expf(-xi[t]));
        float bs = 0.f;
        for (int c = 0; c < C_DIM; c++) {
            float b = beta[t * C_DIM + c];
            bs = fmaf(b, b, bs);
        }
        for (int c = 0; c < C_DIM; c++) {
            float b = beta[t * C_DIM + c];
            g_u[t * C_DIM + c] = (b * b) / bs;
        }
    }
}

// One block = 32 batch rows, 256 threads.
// Phase A: tiled fp32 GEMM (each thread: 2 rows x 4 prototypes) -> si in SMEM.
// Phase B: Dempster scan, 8 lanes per row, 13 mass elements in registers per lane.
__global__ __launch_bounds__(256, 2)
void fused_ds_kernel(const float* __restrict__ x, float* __restrict__ out) {
    __shared__ float xs[ROWS * KC];            // 8 KB, row-major x chunk
    __shared__ float ws[KC * P_DIM];           // 16 KB, k-major w chunk
    __shared__ float sSi[ROWS * SSI_STRIDE];   // padded: conflict-free row-max scan
    __shared__ float sXn[ROWS];
    __shared__ float sMaxR[ROWS];

    const int tid = threadIdx.x;
    const int r0 = blockIdx.x * ROWS;
    const int pr = tid & 15;   // prototype tile (4 p each)
    const int rr = tid >> 4;   // row tile (2 rows each)

    if (tid < ROWS) sXn[tid] = 0.f;
    __syncthreads();

    float acc00 = 0.f, acc01 = 0.f, acc02 = 0.f, acc03 = 0.f;
    float acc10 = 0.f, acc11 = 0.f, acc12 = 0.f, acc13 = 0.f;

    for (int kc = 0; kc < F_DIM; kc += KC) {
        #pragma unroll
        for (int it = 0; it < 2; it++) {
            int idx = tid + it * 256;          // 0..511 float4 slots
            int r = idx >> 4;
            int c4 = (idx & 15) << 2;
            float4 v = *(const float4*)(x + (size_t)(r0 + r) * F_DIM + kc + c4);
            *(float4*)(xs + r * KC + c4) = v;
            atomicAdd(&sXn[r], v.x * v.x + v.y * v.y + v.z * v.z + v.w * v.w);
        }
        #pragma unroll
        for (int it = 0; it < 4; it++) {
            int idx = tid + it * 256;          // 0..1023 float4 slots
            int kk = idx >> 4;
            int c4 = (idx & 15) << 2;
            *(float4*)(ws + kk * P_DIM + c4) =
                *(const float4*)(g_wT + (size_t)(kc + kk) * P_DIM + c4);
        }
        __syncthreads();
        #pragma unroll
        for (int kk = 0; kk < KC; kk += 4) {
            float4 A0 = *(const float4*)(xs + (rr * 2 + 0) * KC + kk);
            float4 A1 = *(const float4*)(xs + (rr * 2 + 1) * KC + kk);
            float a0[4] = {A0.x, A0.y, A0.z, A0.w};
            float a1[4] = {A1.x, A1.y, A1.z, A1.w};
            #pragma unroll
            for (int mI = 0; mI < 4; mI++) {
                float4 Bv = *(const float4*)(ws + (kk + mI) * P_DIM + pr * 4);
                acc00 = fmaf(a0[mI], Bv.x, acc00);
                acc01 = fmaf(a0[mI], Bv.y, acc01);
                acc02 = fmaf(a0[mI], Bv.z, acc02);
                acc03 = fmaf(a0[mI], Bv.w, acc03);
                acc10 = fmaf(a1[mI], Bv.x, acc10);
                acc11 = fmaf(a1[mI], Bv.y, acc11);
                acc12 = fmaf(a1[mI], Bv.z, acc12);
                acc13 = fmaf(a1[mI], Bv.w, acc13);
            }
        }
        __syncthreads();
    }

    // epilogue: si = exp(-gamma*d)*alpha
    {
        float accs[2][4] = {{acc00, acc01, acc02, acc03}, {acc10, acc11, acc12, acc13}};
        #pragma unroll
        for (int j = 0; j < 2; j++) {
            int r = rr * 2 + j;
            float xn = sXn[r];
            #pragma unroll
            for (int i = 0; i < 4; i++) {
                int p = pr * 4 + i;
                float d = xn - 2.f * accs[j][i] + g_wnorm[p];
                sSi[r * SSI_STRIDE + p] = expf(-g_gamma[p] * d) * g_alpha[p];
            }
        }
    }
    __syncthreads();
    if (tid < ROWS) {
        float mx = 0.f;
        #pragma unroll 8
        for (int p = 0; p < P_DIM; p++) mx = fmaxf(mx, sSi[tid * SSI_STRIDE + p]);
        sMaxR[tid] = 1.f / (mx + EPSV);
    }
    __syncthreads();
    #pragma unroll
    for (int j = 0; j < 2; j++) {
        int r = rr * 2 + j;
        float sc = sMaxR[r];
        #pragma unroll
        for (int i = 0; i < 4; i++) sSi[r * SSI_STRIDE + pr * 4 + i] *= sc;
    }
    __syncthreads();

    // ---------------- Phase B: Dempster scan, 8 lanes per row ----------------
    const int lane = tid & 31;
    const int warp = tid >> 5;
    const int g = lane >> 3;          // row-in-warp (4 rows per warp)
    const int q = lane & 7;           // element lane within row group
    const int r = warp * 4 + g;
    const unsigned FULL = 0xffffffffu;
    const int omega_src = (g << 3) + 4;   // lane holding j==100 (q=4, i=12)
    const float* srow = sSi + r * SSI_STRIDE;

    float m[13];
    {
        float s0 = srow[0];
        #pragma unroll
        for (int i = 0; i < 13; i++) {
            int j = q + 8 * i;
            float v;
            if (j < C_DIM)       v = s0 * __ldg(g_u + j);
            else if (j == C_DIM) v = 1.f - s0;
            else                 v = 0.f;
            m[i] = v;
        }
    }
    float om1 = __shfl_sync(FULL, m[12], omega_src);

    for (int p = 1; p < P_DIM; p++) {
        float s = srow[p];
        float a = 1.f - s;
        const float* up = g_u + p * C_DIM;
        float c[13];
        float psum = 0.f;
        #pragma unroll
        for (int i = 0; i < 13; i++) {
            int j = q + 8 * i;
            float cv;
            if (j < C_DIM) {
                float uu = __ldg(up + j);
                cv = fmaf(s * uu, m[i] + om1, a * m[i]);
            } else if (j == C_DIM) {
                cv = 3.f * om1 * a;
            } else {
                cv = 0.f;
            }
            c[i] = cv;
            psum += cv;
        }
        psum += __shfl_xor_sync(FULL, psum, 1);
        psum += __shfl_xor_sync(FULL, psum, 2);
        psum += __shfl_xor_sync(FULL, psum, 4);
        float rinv = 1.f / (psum + EPSV);
        #pragma unroll
        for (int i = 0; i < 13; i++) m[i] = c[i] * rinv;
        om1 = __shfl_sync(FULL, m[12], omega_src);
    }

    // final normalize (no EPS, per reference) and write
    float fs = 0.f;
    #pragma unroll
    for (int i = 0; i < 13; i++) fs += m[i];
    fs += __shfl_xor_sync(FULL, fs, 1);
    fs += __shfl_xor_sync(FULL, fs, 2);
    fs += __shfl_xor_sync(FULL, fs, 4);
    float rnorm = 1.f / fs;

    float* orow = out + (size_t)(r0 + r) * (C_DIM + 1);
    #pragma unroll
    for (int i = 0; i < 13; i++) {
        int j = q + 8 * i;
        if (j <= C_DIM) orow[j] = m[i] * rnorm;
    }
}

extern "C" void kernel_launch(void* const* d_in, const int* in_sizes, int n_in,
                              void* d_out, int out_size) {
    const float* x    = (const float*)d_in[0];
    const float* w    = (const float*)d_in[1];
    const float* xi   = (const float*)d_in[2];
    const float* eta  = (const float*)d_in[3];
    const float* beta = (const float*)d_in[4];
    float* out = (float*)d_out;

    precompute_kernel<<<1, 256>>>(w, xi, eta, beta);
    fused_ds_kernel<<<B_ROWS / ROWS, 256>>>(x, out);
}

// round 2
// speedup vs baseline: 1.8076x; 1.8076x over previous
#include <cuda_runtime.h>
#include <math.h>

#define EPSV 1e-4f
#define BROWS 8192
#define FDIM 512
#define PDIM 64
#define CDIM 100
#define USTRIDE 112   // padded u row (j=100..111 are zero)

typedef unsigned long long ull;

// ---- scratch (device globals; no allocation) ----
__device__ float g_u2[PDIM * USTRIDE];  // normalized beta^2, zero-padded rows
__device__ float g_wnorm[PDIM];
__device__ float g_gamma[PDIM];
__device__ float g_alpha[PDIM];
__device__ float g_si[BROWS * PDIM];

// ---- packed f32x2 helpers (Blackwell; ptxas emits FFMA2 only via PTX) ----
__device__ __forceinline__ ull pk2(float lo, float hi) {
    ull r; asm("mov.b64 %0, {%1, %2};" : "=l"(r) : "f"(lo), "f"(hi)); return r;
}
__device__ __forceinline__ float2 upk2(ull v) {
    float2 r; asm("mov.b64 {%0, %1}, %2;" : "=f"(r.x), "=f"(r.y) : "l"(v)); return r;
}
__device__ __forceinline__ ull fma2(ull a, ull b, ull c) {
    ull d; asm("fma.rn.f32x2 %0, %1, %2, %3;" : "=l"(d) : "l"(a), "l"(b), "l"(c)); return d;
}
__device__ __forceinline__ ull mul2(ull a, ull b) {
    ull d; asm("mul.rn.f32x2 %0, %1, %2;" : "=l"(d) : "l"(a), "l"(b)); return d;
}
__device__ __forceinline__ ull add2(ull a, ull b) {
    ull d; asm("add.rn.f32x2 %0, %1, %2;" : "=l"(d) : "l"(a), "l"(b)); return d;
}
__device__ __forceinline__ float frcp(float x) {
    float r; asm("rcp.approx.f32 %0, %1;" : "=f"(r) : "f"(x)); return r;
}

// ================= precompute: one block per prototype =================
__global__ void precompute_kernel(const float* __restrict__ w,
                                  const float* __restrict__ xi,
                                  const float* __restrict__ eta,
                                  const float* __restrict__ beta) {
    const int p = blockIdx.x;
    const int t = threadIdx.x;   // 128 threads
    __shared__ float red[4], red2[4];

    // ||w_p||^2
    float s = 0.f;
    #pragma unroll
    for (int i = 0; i < 4; i++) {
        float v = w[(size_t)p * FDIM + t + i * 128];
        s = fmaf(v, v, s);
    }
    #pragma unroll
    for (int m = 16; m; m >>= 1) s += __shfl_xor_sync(0xffffffffu, s, m);
    if ((t & 31) == 0) red[t >> 5] = s;

    // sum beta^2
    float b  = (t < CDIM) ? beta[(size_t)p * CDIM + t] : 0.f;
    float bb = b * b;
    float s2 = bb;
    #pragma unroll
    for (int m = 16; m; m >>= 1) s2 += __shfl_xor_sync(0xffffffffu, s2, m);
    if ((t & 31) == 0) red2[t >> 5] = s2;
    __syncthreads();

    if (t == 0) {
        g_wnorm[p] = red[0] + red[1] + red[2] + red[3];
        float e = eta[p];
        g_gamma[p] = e * e;
        g_alpha[p] = 1.f / (1.f + expf(-xi[p]));
    }
    float bs = red2[0] + red2[1] + red2[2] + red2[3];
    if (t < USTRIDE) g_u2[p * USTRIDE + t] = (t < CDIM) ? (bb / bs) : 0.f;
}

// ================= GEMM + si (f32x2 packed along K) =================
#define GROWS 32
#define KC 64
#define XSTR 68   // padded row stride (floats), 16B-aligned

__global__ __launch_bounds__(128, 4)
void gemm_si_kernel(const float* __restrict__ x, const float* __restrict__ w) {
    __shared__ float xs[GROWS * XSTR];   // 8.7 KB
    __shared__ float ws[PDIM * XSTR];    // 17.4 KB
    __shared__ float sXn[GROWS];

    const int tid = threadIdx.x;
    const int r0  = blockIdx.x * GROWS;
    const int rg  = tid >> 4;   // rows rg*4 + j
    const int pg  = tid & 15;   // protos pg*4 + i

    ull acc[4][4];
    #pragma unroll
    for (int j = 0; j < 4; j++)
        #pragma unroll
        for (int i = 0; i < 4; i++) acc[j][i] = 0ull;
    float xnp[4] = {0.f, 0.f, 0.f, 0.f};

    for (int kc = 0; kc < FDIM; kc += KC) {
        // fill x chunk (row-major, coalesced); accumulate ||x||^2 partials
        #pragma unroll
        for (int it = 0; it < 4; it++) {
            int f = tid + it * 128;
            int r = f >> 4, c = f & 15;
            float4 v = *(const float4*)(x + (size_t)(r0 + r) * FDIM + kc + c * 4);
            *(float4*)(xs + r * XSTR + c * 4) = v;
            xnp[it] += v.x * v.x + v.y * v.y + v.z * v.z + v.w * v.w;
        }
        // fill w chunk straight from w (row-major, coalesced)
        #pragma unroll
        for (int it = 0; it < 8; it++) {
            int f = tid + it * 128;
            int pr = f >> 4, c = f & 15;
            *(float4*)(ws + pr * XSTR + c * 4) =
                *(const float4*)(w + (size_t)pr * FDIM + kc + c * 4);
        }
        __syncthreads();

        #pragma unroll
        for (int kk = 0; kk < KC; kk += 4) {
            ulonglong2 a2[4], b2[4];
            #pragma unroll
            for (int j = 0; j < 4; j++)
                a2[j] = *(const ulonglong2*)(xs + (rg * 4 + j) * XSTR + kk);
            #pragma unroll
            for (int i = 0; i < 4; i++)
                b2[i] = *(const ulonglong2*)(ws + (pg * 4 + i) * XSTR + kk);
            #pragma unroll
            for (int j = 0; j < 4; j++)
                #pragma unroll
                for (int i = 0; i < 4; i++) {
                    acc[j][i] = fma2(a2[j].x, b2[i].x, acc[j][i]);
                    acc[j][i] = fma2(a2[j].y, b2[i].y, acc[j][i]);
                }
        }
        __syncthreads();
    }

    // reduce ||x||^2 partials: 16 consecutive tids hold the same rows
    #pragma unroll
    for (int it = 0; it < 4; it++) {
        float v = xnp[it];
        v += __shfl_xor_sync(0xffffffffu, v, 1);
        v += __shfl_xor_sync(0xffffffffu, v, 2);
        v += __shfl_xor_sync(0xffffffffu, v, 4);
        v += __shfl_xor_sync(0xffffffffu, v, 8);
        if ((tid & 15) == 0) sXn[(tid >> 4) + 8 * it] = v;
    }
    __syncthreads();

    // epilogue: si = exp(-gamma*d)*alpha, row-max normalize, store
    #pragma unroll
    for (int j = 0; j < 4; j++) {
        const int row = rg * 4 + j;
        const float xn = sXn[row];
        float sv[4];
        float mx = 0.f;
        #pragma unroll
        for (int i = 0; i < 4; i++) {
            int p = pg * 4 + i;
            float2 dv = upk2(acc[j][i]);
            float dot = dv.x + dv.y;
            float d = xn - 2.f * dot + __ldg(g_wnorm + p);
            float si = expf(-__ldg(g_gamma + p) * d) * __ldg(g_alpha + p);
            sv[i] = si;
            mx = fmaxf(mx, si);
        }
        mx = fmaxf(mx, __shfl_xor_sync(0xffffffffu, mx, 1));
        mx = fmaxf(mx, __shfl_xor_sync(0xffffffffu, mx, 2));
        mx = fmaxf(mx, __shfl_xor_sync(0xffffffffu, mx, 4));
        mx = fmaxf(mx, __shfl_xor_sync(0xffffffffu, mx, 8));
        float inv = 1.f / (mx + EPSV);
        float4 o;
        o.x = sv[0] * inv; o.y = sv[1] * inv; o.z = sv[2] * inv; o.w = sv[3] * inv;
        *(float4*)(g_si + (size_t)(r0 + row) * PDIM + pg * 4) = o;
    }
}

// ================= Dempster scan (packed f32x2, norm every 2 steps) =================
#define SROWS 16
#define OSTRIDE 102

__global__ __launch_bounds__(128, 4)
void scan_kernel(float* __restrict__ out) {
    __shared__ float sU[PDIM * USTRIDE];     // 28.7 KB
    __shared__ float sSi[SROWS * 65];
    __shared__ float sOut[SROWS * OSTRIDE];

    const int tid = threadIdx.x;
    const int r0  = blockIdx.x * SROWS;

    // stage u (flat float4 copy of padded table)
    for (int f = tid; f < PDIM * USTRIDE / 4; f += 128)
        *(float4*)(sU + f * 4) = *(const float4*)(g_u2 + f * 4);
    // stage si rows
    #pragma unroll
    for (int it = 0; it < 2; it++) {
        int f = tid + it * 128;
        int r = f >> 4, c = f & 15;
        float4 v = *(const float4*)(g_si + (size_t)(r0 + r) * PDIM + c * 4);
        sSi[r * 65 + c * 4 + 0] = v.x;
        sSi[r * 65 + c * 4 + 1] = v.y;
        sSi[r * 65 + c * 4 + 2] = v.z;
        sSi[r * 65 + c * 4 + 3] = v.w;
    }
    __syncthreads();

    const unsigned FULL = 0xffffffffu;
    const int lane = tid & 31;
    const int warp = tid >> 5;
    const int g = lane >> 3;          // row within warp
    const int q = lane & 7;           // element-lane: pairs j = 2q + 16i
    const int r = warp * 4 + g;
    const int omsrc = (g << 3) + 2;   // lane holding j==100 (pair 6, .x)
    const float* srow = sSi + r * 65;

    const ull fix6 = pk2((q == 2) ? 3.f : 1.f, 1.f);

    // init with prototype 0
    ull m[7];
    {
        float s0 = srow[0];
        ull s0p = pk2(s0, s0);
        const float* u0 = sU + 2 * q;
        #pragma unroll
        for (int i = 0; i < 7; i++)
            m[i] = mul2(s0p, *(const ull*)(u0 + 16 * i));
        if (q == 2) m[6] = pk2(1.f - s0, 0.f);
    }
    float om1 = __shfl_sync(FULL, upk2(m[6]).x, omsrc);

    // sequential combine over prototypes 1..63 (scale-free; renorm every 2 steps)
    for (int p = 1; p < PDIM; p++) {
        float s = srow[p];
        float a = 1.f - s;
        float g1 = s * om1;
        ull sp = pk2(s, s), ap = pk2(a, a), g1p = pk2(g1, g1);
        const float* up = sU + p * USTRIDE + 2 * q;
        ull c[7];
        #pragma unroll
        for (int i = 0; i < 7; i++) {
            ull u2 = *(const ull*)(up + 16 * i);
            ull f  = fma2(sp, u2, ap);      // s*u + a
            ull t  = mul2(m[i], f);         // m*(s*u+a)
            c[i]   = fma2(g1p, u2, t);      // + s*om1*u
        }
        c[6] = mul2(c[6], fix6);            // omega slot: a*om -> 3*a*om
        float omraw = __shfl_sync(FULL, upk2(c[6]).x, omsrc);

        if (p & 1) {
            ull ps = c[0];
            #pragma unroll
            for (int i = 1; i < 7; i++) ps = add2(ps, c[i]);
            float2 pv = upk2(ps);
            float psum = pv.x + pv.y;
            psum += __shfl_xor_sync(FULL, psum, 1);
            psum += __shfl_xor_sync(FULL, psum, 2);
            psum += __shfl_xor_sync(FULL, psum, 4);
            float rinv = frcp(psum);
            ull rp = pk2(rinv, rinv);
            #pragma unroll
            for (int i = 0; i < 7; i++) m[i] = mul2(c[i], rp);
            om1 = omraw * rinv;
        } else {
            #pragma unroll
            for (int i = 0; i < 7; i++) m[i] = c[i];
            om1 = omraw;
        }
    }

    // final exact-style normalization (scale removed here)
    {
        ull ps = m[0];
        #pragma unroll
        for (int i = 1; i < 7; i++) ps = add2(ps, m[i]);
        float2 pv = upk2(ps);
        float fs = pv.x + pv.y;
        fs += __shfl_xor_sync(FULL, fs, 1);
        fs += __shfl_xor_sync(FULL, fs, 2);
        fs += __shfl_xor_sync(FULL, fs, 4);
        float rn = 1.f / fs;

        float* orow = sOut + r * OSTRIDE;
        #pragma unroll
        for (int i = 0; i < 6; i++) {
            float2 mv = upk2(m[i]);
            int j = 2 * q + 16 * i;
            *(float2*)(orow + j) = make_float2(mv.x * rn, mv.y * rn);
        }
        float2 mv = upk2(m[6]);
        int j = 96 + 2 * q;
        if (q < 2)       *(float2*)(orow + j) = make_float2(mv.x * rn, mv.y * rn);
        else if (q == 2) orow[100] = mv.x * rn;
    }
    __syncthreads();

    // coalesced output copy (block's rows are contiguous in out)
    for (int idx = tid; idx < SROWS * (CDIM + 1); idx += 128) {
        int rr = idx / (CDIM + 1);
        int jj = idx - rr * (CDIM + 1);
        out[(size_t)r0 * (CDIM + 1) + idx] = sOut[rr * OSTRIDE + jj];
    }
}

extern "C" void kernel_launch(void* const* d_in, const int* in_sizes, int n_in,
                              void* d_out, int out_size) {
    const float* x    = (const float*)d_in[0];
    const float* w    = (const float*)d_in[1];
    const float* xi   = (const float*)d_in[2];
    const float* eta  = (const float*)d_in[3];
    const float* beta = (const float*)d_in[4];
    float* out = (float*)d_out;

    precompute_kernel<<<PDIM, 128>>>(w, xi, eta, beta);
    gemm_si_kernel<<<BROWS / GROWS, 128>>>(x, w);
    scan_kernel<<<BROWS / SROWS, 128>>>(out);
}

// round 4
// speedup vs baseline: 3.0097x; 1.6651x over previous
#include <cuda_runtime.h>
#include <cstdint>
#include <math.h>

#define EPSV 1e-4f
#define BROWS 8192
#define FDIM 512
#define PDIM 64
#define CDIM 100
#define USTRIDE 112   // padded u row (j=100..111 are zero)

typedef unsigned long long ull;

// ---- scratch (device globals; no allocation) ----
__device__ float g_u2[PDIM * USTRIDE];  // normalized beta^2, zero-padded rows
__device__ float g_wnorm[PDIM];
__device__ float g_gamma[PDIM];
__device__ float g_alpha[PDIM];
__device__ float g_si[BROWS * PDIM];

// ---- packed f32x2 helpers (ptxas emits FFMA2 only via PTX) ----
__device__ __forceinline__ ull pk2(float lo, float hi) {
    ull r; asm("mov.b64 %0, {%1, %2};" : "=l"(r) : "f"(lo), "f"(hi)); return r;
}
__device__ __forceinline__ float2 upk2(ull v) {
    float2 r; asm("mov.b64 {%0, %1}, %2;" : "=f"(r.x), "=f"(r.y) : "l"(v)); return r;
}
__device__ __forceinline__ ull fma2(ull a, ull b, ull c) {
    ull d; asm("fma.rn.f32x2 %0, %1, %2, %3;" : "=l"(d) : "l"(a), "l"(b), "l"(c)); return d;
}
__device__ __forceinline__ ull mul2(ull a, ull b) {
    ull d; asm("mul.rn.f32x2 %0, %1, %2;" : "=l"(d) : "l"(a), "l"(b)); return d;
}
__device__ __forceinline__ ull add2(ull a, ull b) {
    ull d; asm("add.rn.f32x2 %0, %1, %2;" : "=l"(d) : "l"(a), "l"(b)); return d;
}
__device__ __forceinline__ float frcp(float x) {
    float r; asm("rcp.approx.f32 %0, %1;" : "=f"(r) : "f"(x)); return r;
}
__device__ __forceinline__ unsigned int s2u(const void* p) {
    return (unsigned int)__cvta_generic_to_shared(p);
}
__device__ __forceinline__ void cpa16(unsigned int dst, const void* src) {
    asm volatile("cp.async.cg.shared.global [%0], [%1], 16;" :: "r"(dst), "l"(src));
}

// ================= precompute: one block per prototype =================
__global__ void precompute_kernel(const float* __restrict__ w,
                                  const float* __restrict__ xi,
                                  const float* __restrict__ eta,
                                  const float* __restrict__ beta) {
    const int p = blockIdx.x;
    const int t = threadIdx.x;   // 128 threads
    __shared__ float red[4], red2[4];

    float s = 0.f;
    #pragma unroll
    for (int i = 0; i < 4; i++) {
        float v = w[(size_t)p * FDIM + t + i * 128];
        s = fmaf(v, v, s);
    }
    #pragma unroll
    for (int m = 16; m; m >>= 1) s += __shfl_xor_sync(0xffffffffu, s, m);
    if ((t & 31) == 0) red[t >> 5] = s;

    float b  = (t < CDIM) ? beta[(size_t)p * CDIM + t] : 0.f;
    float bb = b * b;
    float s2 = bb;
    #pragma unroll
    for (int m = 16; m; m >>= 1) s2 += __shfl_xor_sync(0xffffffffu, s2, m);
    if ((t & 31) == 0) red2[t >> 5] = s2;
    __syncthreads();

    if (t == 0) {
        g_wnorm[p] = red[0] + red[1] + red[2] + red[3];
        float e = eta[p];
        g_gamma[p] = e * e;
        g_alpha[p] = 1.f / (1.f + expf(-xi[p]));
    }
    float bs = red2[0] + red2[1] + red2[2] + red2[3];
    if (t < USTRIDE) g_u2[p * USTRIDE + t] = (t < CDIM) ? (bb / bs) : 0.f;
}

// ================= GEMM + si =================
// 64 threads/block, block tile 32 rows x 64 protos, thread tile 4 rows x 8 protos.
// f32x2 packed along K; XOR-swizzled smem (conflict-free); cp.async double buffer.
#define GROWS 32
#define KC 64

__device__ __forceinline__ void stage_chunk(float* xsb, float* wsb,
                                            const float* __restrict__ x,
                                            const float* __restrict__ w,
                                            int r0, int kc, int tid) {
    #pragma unroll
    for (int it = 0; it < 8; it++) {
        int f = tid + it * 64;
        int row = f >> 4, c = f & 15;
        unsigned int dst = s2u(xsb + row * 64 + ((c * 4) ^ ((row >> 2) << 2)));
        cpa16(dst, x + (size_t)(r0 + row) * FDIM + kc + c * 4);
    }
    #pragma unroll
    for (int it = 0; it < 16; it++) {
        int f = tid + it * 64;
        int p = f >> 4, c = f & 15;
        unsigned int dst = s2u(wsb + p * 64 + ((c * 4) ^ ((p >> 3) << 2)));
        cpa16(dst, w + (size_t)p * FDIM + kc + c * 4);
    }
    asm volatile("cp.async.commit_group;" ::: "memory");
}

__global__ __launch_bounds__(64)
void gemm_si_kernel(const float* __restrict__ x, const float* __restrict__ w) {
    __shared__ __align__(16) float xs[2][GROWS * KC];   // 2 x 8 KB
    __shared__ __align__(16) float ws[2][PDIM * KC];    // 2 x 16 KB

    const int tid = threadIdx.x;
    const int r0  = blockIdx.x * GROWS;
    const int rg  = tid >> 3;   // 0..7 : rows rg*4 + j
    const int pg  = tid & 7;    // 0..7 : protos pg*8 + i

    ull acc[4][8];
    #pragma unroll
    for (int j = 0; j < 4; j++)
        #pragma unroll
        for (int i = 0; i < 8; i++) acc[j][i] = 0ull;
    ull xn2[4] = {0ull, 0ull, 0ull, 0ull};

    stage_chunk(xs[0], ws[0], x, w, r0, 0, tid);

    #pragma unroll 1
    for (int ch = 0; ch < FDIM / KC; ch++) {
        const int buf = ch & 1;
        if (ch < FDIM / KC - 1) {
            stage_chunk(xs[buf ^ 1], ws[buf ^ 1], x, w, r0, (ch + 1) * KC, tid);
            asm volatile("cp.async.wait_group 1;" ::: "memory");
        } else {
            asm volatile("cp.async.wait_group 0;" ::: "memory");
        }
        __syncthreads();

        const float* xb = xs[buf];
        const float* wb = ws[buf];
        #pragma unroll
        for (int kk = 0; kk < KC; kk += 4) {
            ulonglong2 a2[4], b2[8];
            #pragma unroll
            for (int j = 0; j < 4; j++)
                a2[j] = *(const ulonglong2*)(xb + ((rg * 4 + j) << 6) + (kk ^ (rg << 2)));
            #pragma unroll
            for (int i = 0; i < 8; i++)
                b2[i] = *(const ulonglong2*)(wb + ((pg * 8 + i) << 6) + (kk ^ (pg << 2)));
            #pragma unroll
            for (int j = 0; j < 4; j++) {
                xn2[j] = fma2(a2[j].x, a2[j].x, xn2[j]);
                xn2[j] = fma2(a2[j].y, a2[j].y, xn2[j]);
                #pragma unroll
                for (int i = 0; i < 8; i++) {
                    acc[j][i] = fma2(a2[j].x, b2[i].x, acc[j][i]);
                    acc[j][i] = fma2(a2[j].y, b2[i].y, acc[j][i]);
                }
            }
        }
        __syncthreads();
    }

    // epilogue: si = exp(-gamma*d)*alpha, row-max normalize, store
    const unsigned FULL = 0xffffffffu;
    #pragma unroll
    for (int j = 0; j < 4; j++) {
        const int row = rg * 4 + j;
        float2 xv = upk2(xn2[j]);
        const float xn = xv.x + xv.y;
        float sv[8];
        float mx = 0.f;
        #pragma unroll
        for (int i = 0; i < 8; i++) {
            int p = pg * 8 + i;
            float2 dv = upk2(acc[j][i]);
            float d = xn - 2.f * (dv.x + dv.y) + __ldg(g_wnorm + p);
            float si = __expf(-__ldg(g_gamma + p) * d) * __ldg(g_alpha + p);
            sv[i] = si;
            mx = fmaxf(mx, si);
        }
        mx = fmaxf(mx, __shfl_xor_sync(FULL, mx, 1));
        mx = fmaxf(mx, __shfl_xor_sync(FULL, mx, 2));
        mx = fmaxf(mx, __shfl_xor_sync(FULL, mx, 4));
        float inv = 1.f / (mx + EPSV);
        float4 o0, o1;
        o0.x = sv[0] * inv; o0.y = sv[1] * inv; o0.z = sv[2] * inv; o0.w = sv[3] * inv;
        o1.x = sv[4] * inv; o1.y = sv[5] * inv; o1.z = sv[6] * inv; o1.w = sv[7] * inv;
        *(float4*)(g_si + (size_t)(r0 + row) * PDIM + pg * 8)     = o0;
        *(float4*)(g_si + (size_t)(r0 + row) * PDIM + pg * 8 + 4) = o1;
    }
}

// ================= Dempster scan =================
// 32 rows/block, 256 threads; omega tracked per-lane (no per-step shfl);
// normalize every 4 steps (scale-invariant; final normalize removes scale).
#define SROWS 32
#define OSTRIDE 102

__global__ __launch_bounds__(256)
void scan_kernel(float* __restrict__ out) {
    __shared__ float sU[PDIM * USTRIDE];     // 28.7 KB
    __shared__ float sSi[SROWS * 65];        // 8.3 KB
    __shared__ float sOut[SROWS * OSTRIDE];  // 13.1 KB

    const int tid = threadIdx.x;
    const int r0  = blockIdx.x * SROWS;

    for (int f = tid; f < PDIM * USTRIDE / 4; f += 256)
        *(float4*)(sU + f * 4) = *(const float4*)(g_u2 + f * 4);
    #pragma unroll
    for (int it = 0; it < 2; it++) {
        int f = tid + it * 256;
        int r = f >> 4, c = f & 15;
        float4 v = *(const float4*)(g_si + (size_t)(r0 + r) * PDIM + c * 4);
        sSi[r * 65 + c * 4 + 0] = v.x;
        sSi[r * 65 + c * 4 + 1] = v.y;
        sSi[r * 65 + c * 4 + 2] = v.z;
        sSi[r * 65 + c * 4 + 3] = v.w;
    }
    __syncthreads();

    const unsigned FULL = 0xffffffffu;
    const int lane = tid & 31;
    const int warp = tid >> 5;
    const int g = lane >> 3;          // row within warp
    const int q = lane & 7;           // element-lane: pairs j = 2q + 16i
    const int r = warp * 4 + g;
    const float* srow = sSi + r * 65;

    const ull fix6 = pk2((q == 2) ? 3.f : 1.f, 1.f);

    // init with prototype 0; omega tracked redundantly in every lane
    ull m[7];
    float om;
    {
        float s0 = srow[0];
        ull s0p = pk2(s0, s0);
        const float* u0 = sU + 2 * q;
        #pragma unroll
        for (int i = 0; i < 7; i++)
            m[i] = mul2(s0p, *(const ull*)(u0 + 16 * i));
        om = 1.f - s0;
        if (q == 2) m[6] = pk2(om, 0.f);
    }

    for (int p = 1; p < PDIM; p++) {
        float s = srow[p];
        float a = 1.f - s;
        float g1 = s * om;
        float om_new = 3.f * a * om;       // scalar omega recurrence (pre-norm)
        ull sp = pk2(s, s), ap = pk2(a, a), g1p = pk2(g1, g1);
        const float* up = sU + p * USTRIDE + 2 * q;
        ull c[7];
        #pragma unroll
        for (int i = 0; i < 7; i++) {
            ull u2 = *(const ull*)(up + 16 * i);
            ull f  = fma2(sp, u2, ap);      // s*u + a
            ull t  = mul2(m[i], f);         // m*(s*u+a)
            c[i]   = fma2(g1p, u2, t);      // + s*om*u
        }
        c[6] = mul2(c[6], fix6);            // omega slot (q==2,lo): a*om -> 3*a*om

        if ((p & 3) == 3) {
            ull ps = c[0];
            #pragma unroll
            for (int i = 1; i < 7; i++) ps = add2(ps, c[i]);
            float2 pv = upk2(ps);
            float psum = pv.x + pv.y;
            psum += __shfl_xor_sync(FULL, psum, 1);
            psum += __shfl_xor_sync(FULL, psum, 2);
            psum += __shfl_xor_sync(FULL, psum, 4);
            float rinv = frcp(psum);
            ull rp = pk2(rinv, rinv);
            #pragma unroll
            for (int i = 0; i < 7; i++) m[i] = mul2(c[i], rp);
            om = om_new * rinv;
        } else {
            #pragma unroll
            for (int i = 0; i < 7; i++) m[i] = c[i];
            om = om_new;
        }
    }

    // final exact normalization
    {
        ull ps = m[0];
        #pragma unroll
        for (int i = 1; i < 7; i++) ps = add2(ps, m[i]);
        float2 pv = upk2(ps);
        float fs = pv.x + pv.y;
        fs += __shfl_xor_sync(FULL, fs, 1);
        fs += __shfl_xor_sync(FULL, fs, 2);
        fs += __shfl_xor_sync(FULL, fs, 4);
        float rn = 1.f / fs;

        float* orow = sOut + r * OSTRIDE;
        #pragma unroll
        for (int i = 0; i < 6; i++) {
            float2 mv = upk2(m[i]);
            int j = 2 * q + 16 * i;
            *(float2*)(orow + j) = make_float2(mv.x * rn, mv.y * rn);
        }
        float2 mv = upk2(m[6]);
        int j = 96 + 2 * q;
        if (q < 2)       *(float2*)(orow + j) = make_float2(mv.x * rn, mv.y * rn);
        else if (q == 2) orow[100] = mv.x * rn;
    }
    __syncthreads();

    for (int idx = tid; idx < SROWS * (CDIM + 1); idx += 256) {
        int rr = idx / (CDIM + 1);
        int jj = idx - rr * (CDIM + 1);
        out[(size_t)r0 * (CDIM + 1) + idx] = sOut[rr * OSTRIDE + jj];
    }
}

extern "C" void kernel_launch(void* const* d_in, const int* in_sizes, int n_in,
                              void* d_out, int out_size) {
    const float* x    = (const float*)d_in[0];
    const float* w    = (const float*)d_in[1];
    const float* xi   = (const float*)d_in[2];
    const float* eta  = (const float*)d_in[3];
    const float* beta = (const float*)d_in[4];
    float* out = (float*)d_out;

    precompute_kernel<<<PDIM, 128>>>(w, xi, eta, beta);
    gemm_si_kernel<<<BROWS / GROWS, 64>>>(x, w);
    scan_kernel<<<BROWS / SROWS, 256>>>(out);
}